// round 7
// baseline (speedup 1.0000x reference)
#include <cuda_runtime.h>

static constexpr int NPIX   = 256 * 256;   // pixels per batch
static constexpr int NBATCH = 16;
static constexpr int NBINS  = 64;
static constexpr int BPB    = 9;           // blocks per batch (9*16=144 ~ one wave)
static constexpr int TPB    = 256;

// encoded global min/max: [ref_min, ref_max, tar_min, tar_max]
__device__ unsigned g_mm[4];

// Monotone float->uint encoding (works for negatives too)
__device__ __forceinline__ unsigned fenc(float f) {
    unsigned b = __float_as_uint(f);
    return (b & 0x80000000u) ? ~b : (b | 0x80000000u);
}
__device__ __forceinline__ float fdec(unsigned e) {
    unsigned b = (e & 0x80000000u) ? (e & 0x7fffffffu) : ~e;
    return __uint_as_float(b);
}

__global__ void k_init(float* __restrict__ out, int n) {
    int i = blockIdx.x * blockDim.x + threadIdx.x;
    if (i < n) out[i] = 0.0f;
    if (i == 0) {
        g_mm[0] = 0xFFFFFFFFu; g_mm[1] = 0u;   // ref min/max
        g_mm[2] = 0xFFFFFFFFu; g_mm[3] = 0u;   // tar min/max
    }
}

__global__ void k_minmax(const float4* __restrict__ ref,
                         const float4* __restrict__ tar, int n4) {
    unsigned rmin = 0xFFFFFFFFu, rmax = 0u, tmin = 0xFFFFFFFFu, tmax = 0u;
    for (int i = blockIdx.x * blockDim.x + threadIdx.x; i < n4;
         i += gridDim.x * blockDim.x) {
        float4 a = ref[i];
        unsigned e;
        e = fenc(a.x); rmin = min(rmin, e); rmax = max(rmax, e);
        e = fenc(a.y); rmin = min(rmin, e); rmax = max(rmax, e);
        e = fenc(a.z); rmin = min(rmin, e); rmax = max(rmax, e);
        e = fenc(a.w); rmin = min(rmin, e); rmax = max(rmax, e);
        float4 b = tar[i];
        e = fenc(b.x); tmin = min(tmin, e); tmax = max(tmax, e);
        e = fenc(b.y); tmin = min(tmin, e); tmax = max(tmax, e);
        e = fenc(b.z); tmin = min(tmin, e); tmax = max(tmax, e);
        e = fenc(b.w); tmin = min(tmin, e); tmax = max(tmax, e);
    }
    #pragma unroll
    for (int o = 16; o > 0; o >>= 1) {
        rmin = min(rmin, __shfl_xor_sync(0xFFFFFFFFu, rmin, o));
        rmax = max(rmax, __shfl_xor_sync(0xFFFFFFFFu, rmax, o));
        tmin = min(tmin, __shfl_xor_sync(0xFFFFFFFFu, tmin, o));
        tmax = max(tmax, __shfl_xor_sync(0xFFFFFFFFu, tmax, o));
    }
    if ((threadIdx.x & 31) == 0) {
        atomicMin(&g_mm[0], rmin);
        atomicMax(&g_mm[1], rmax);
        atomicMin(&g_mm[2], tmin);
        atomicMax(&g_mm[3], tmax);
    }
}

// Closed-form cubic B-spline weights at offsets {-1-u, -u, 1-u, 2-u}
__device__ __forceinline__ void bsw(float u, float w[4]) {
    float v = 1.0f - u;
    w[0] = v * v * v * (1.0f / 6.0f);                 // bin f-1
    w[1] = 2.0f / 3.0f - u * u * (1.0f - 0.5f * u);   // bin f
    w[2] = 2.0f / 3.0f - v * v * (1.0f - 0.5f * v);   // bin f+1
    w[3] = u * u * u * (1.0f / 6.0f);                 // bin f+2
}

__device__ __forceinline__ void accum(float r, float t,
                                      float rmin, float rs,
                                      float tmin, float ts,
                                      float* __restrict__ sh) {
    float fr = (r - rmin) * rs;          // in [0, 64]
    float ft = (t - tmin) * ts;
    float fir = floorf(fr), fit = floorf(ft);
    float ur = fr - fir,   ut = ft - fit;
    int br = (int)fir - 1, bt = (int)fit - 1;
    float wr[4], wt[4];
    bsw(ur, wr);
    bsw(ut, wt);
    #pragma unroll
    for (int i = 0; i < 4; i++) {
        int bi = br + i;
        if ((unsigned)bi >= (unsigned)NBINS) continue;
        float wrv = wr[i];
        #pragma unroll
        for (int j = 0; j < 4; j++) {
            int bj = bt + j;
            if ((unsigned)bj >= (unsigned)NBINS) continue;
            atomicAdd(&sh[bi * NBINS + bj], wrv * wt[j]);
        }
    }
}

__global__ __launch_bounds__(TPB)
void k_hist(const float4* __restrict__ ref,
            const float4* __restrict__ tar,
            float* __restrict__ out) {
    __shared__ float sh[NBINS * NBINS];
    const int batch = blockIdx.y;

    for (int i = threadIdx.x; i < NBINS * NBINS; i += TPB) sh[i] = 0.0f;
    __syncthreads();

    const float rmin = fdec(g_mm[0]);
    const float rmax = fdec(g_mm[1]);
    const float tmin = fdec(g_mm[2]);
    const float tmax = fdec(g_mm[3]);
    const float rs = 64.0f / (rmax - rmin);
    const float ts = 64.0f / (tmax - tmin);

    const float4* rp = ref + (size_t)batch * (NPIX / 4);
    const float4* tp = tar + (size_t)batch * (NPIX / 4);

    for (int i = blockIdx.x * TPB + threadIdx.x; i < NPIX / 4; i += BPB * TPB) {
        float4 r4 = rp[i];
        float4 t4 = tp[i];
        accum(r4.x, t4.x, rmin, rs, tmin, ts, sh);
        accum(r4.y, t4.y, rmin, rs, tmin, ts, sh);
        accum(r4.z, t4.z, rmin, rs, tmin, ts, sh);
        accum(r4.w, t4.w, rmin, rs, tmin, ts, sh);
    }
    __syncthreads();

    float* o = out + (size_t)batch * NBINS * NBINS;
    for (int i = threadIdx.x; i < NBINS * NBINS; i += TPB) {
        // / (EPS*EPS) = * 4096
        atomicAdd(&o[i], sh[i] * 4096.0f);
    }
}

extern "C" void kernel_launch(void* const* d_in, const int* in_sizes, int n_in,
                              void* d_out, int out_size) {
    const float* img_ref = (const float*)d_in[0];
    const float* img_tar = (const float*)d_in[1];
    float* out = (float*)d_out;

    // 1) zero output + reset min/max cells
    k_init<<<(out_size + 255) / 256, 256>>>(out, out_size);

    // 2) global min/max over each full image (NBATCH*NPIX elements each)
    const int n4 = NBATCH * NPIX / 4;
    k_minmax<<<296, 256>>>((const float4*)img_ref, (const float4*)img_tar, n4);

    // 3) joint histogram
    dim3 grid(BPB, NBATCH);
    k_hist<<<grid, TPB>>>((const float4*)img_ref, (const float4*)img_tar, out);
}